// round 7
// baseline (speedup 1.0000x reference)
#include <cuda_runtime.h>
#include <cuda_bf16.h>
#include <math.h>

// Problem dims
#define BB 1024
#define TT 128
#define EE 300
#define HH 100
#define GG 400     // 4*H
#define VV 50000
#define NB 8       // batches per LSTM CTA
#define NTILES 50  // GG/8 (permuted gate-interleaved layout)
#define KTILES 13  // ceil(HH/8)
#define LSTM_THREADS 576
#define PB_STRIDE 408   // Pbuf row pad (floats), 16B-aligned, 2-way LDS conflicts max
#define HO_STRIDE 104   // Hout row pad (floats), 16B-aligned

// Scratch (device globals -- no allocation allowed)
// g_P is stored COLUMN-PERMUTED: permuted col p holds orig col (p&3)*100+(p>>2)
__device__ float g_P[VV * GG];
__device__ float g_out[BB * TT * HH]; // hidden states (52 MB)
__device__ float g_last[BB * HH];
__device__ float g_label[BB * HH];
__device__ float g_q[BB * 6];
__device__ float g_probe;

// ---------------- PTX helpers ----------------
__device__ __forceinline__ unsigned f2tf32(float x) {
    unsigned u;
    asm("cvt.rna.tf32.f32 %0, %1;" : "=r"(u) : "f"(x));
    return u;
}

__device__ __forceinline__ void mma_tf32(float* d, const unsigned* a, const unsigned* b) {
    asm volatile(
        "mma.sync.aligned.m16n8k8.row.col.f32.tf32.tf32.f32 "
        "{%0,%1,%2,%3}, {%4,%5,%6,%7}, {%8,%9}, {%0,%1,%2,%3};"
        : "+f"(d[0]), "+f"(d[1]), "+f"(d[2]), "+f"(d[3])
        : "r"(a[0]), "r"(a[1]), "r"(a[2]), "r"(a[3]), "r"(b[0]), "r"(b[1]));
}

// Rows 8..15 of A are zero padding -> a1,a3 = 0. d[2],d[3] are per-tile junk
// slots (MUST be per-tile: sharing them across tiles serializes the HMMA chain).
__device__ __forceinline__ void mma_tf32_half4(float* d, unsigned a0, unsigned a2,
                                               unsigned b0, unsigned b1) {
    asm volatile(
        "mma.sync.aligned.m16n8k8.row.col.f32.tf32.tf32.f32 "
        "{%0,%1,%2,%3}, {%4,%5,%6,%7}, {%8,%9}, {%0,%1,%2,%3};"
        : "+f"(d[0]), "+f"(d[1]), "+f"(d[2]), "+f"(d[3])
        : "r"(a0), "r"(0u), "r"(a2), "r"(0u), "r"(b0), "r"(b1));
}

// HW tanh (sm_75+): single MUFU op, ~2^-11 abs error
__device__ __forceinline__ float tanh_hw(float x) {
    float y;
    asm("tanh.approx.f32 %0, %1;" : "=f"(y) : "f"(x));
    return y;
}
__device__ __forceinline__ float sigm_hw(float x) {
    return fmaf(tanh_hw(0.5f * x), 0.5f, 0.5f);
}

// ---------------------------------------------------------------------------
// Kernel 1: P[v, p] = sum_e emb[v,e]*W_ih[orig(p),e] + bias[orig(p)]
// Permutation applied at B-LOAD time -> epilogue stores are contiguous.
// tf32 mma GEMM, 128x64 CTA tile, BK=16, double-buffered smem + reg prefetch.
// ---------------------------------------------------------------------------
#define AS_STRIDE 132
#define BS_STRIDE 68
#define NITER 19   // ceil(300/16)

__global__ void gemm_P_kernel(const float* __restrict__ emb,
                              const float* __restrict__ W_ih,
                              const float* __restrict__ b_ih,
                              const float* __restrict__ b_hh) {
    __shared__ unsigned As[2][16 * AS_STRIDE];
    __shared__ unsigned Bs[2][16 * BS_STRIDE];

    const int m0 = blockIdx.y * 128;
    const int n0 = blockIdx.x * 64;   // permuted-column block
    const int tid = threadIdx.x;
    const int lane = tid & 31;
    const int wid = tid >> 5;
    const int warp_m = wid & 3;
    const int warp_n = wid >> 2;

    float acc[2][4][4];
#pragma unroll
    for (int mt = 0; mt < 2; mt++)
#pragma unroll
        for (int nt = 0; nt < 4; nt++)
#pragma unroll
            for (int c = 0; c < 4; c++) acc[mt][nt][c] = 0.f;

    float4 ra[2], rb;
    const int aq = tid & 3;
    const int am0 = (tid >> 2);
    const int bq = tid & 3;
    const int bn = tid >> 2;
    const int gn_p = n0 + bn;
    const int gn_orig = (gn_p & 3) * 100 + (gn_p >> 2);

    auto loadAB = [&](int it) {
        int k0 = it * 16;
#pragma unroll
        for (int i = 0; i < 2; i++) {
            int m = am0 + i * 64;
            int gm = m0 + m;
            int gk = k0 + aq * 4;
            ra[i] = make_float4(0.f, 0.f, 0.f, 0.f);
            if (gm < VV && gk < EE)
                ra[i] = *reinterpret_cast<const float4*>(&emb[gm * EE + gk]);
        }
        int gk = k0 + bq * 4;
        rb = make_float4(0.f, 0.f, 0.f, 0.f);
        if (gn_p < GG && gk < EE)
            rb = *reinterpret_cast<const float4*>(&W_ih[gn_orig * EE + gk]);
    };

    loadAB(0);

    for (int it = 0; it < NITER; it++) {
        const int buf = it & 1;
#pragma unroll
        for (int i = 0; i < 2; i++) {
            int m = am0 + i * 64;
            As[buf][(aq * 4 + 0) * AS_STRIDE + m] = __float_as_uint(ra[i].x);
            As[buf][(aq * 4 + 1) * AS_STRIDE + m] = __float_as_uint(ra[i].y);
            As[buf][(aq * 4 + 2) * AS_STRIDE + m] = __float_as_uint(ra[i].z);
            As[buf][(aq * 4 + 3) * AS_STRIDE + m] = __float_as_uint(ra[i].w);
        }
        Bs[buf][(bq * 4 + 0) * BS_STRIDE + bn] = __float_as_uint(rb.x);
        Bs[buf][(bq * 4 + 1) * BS_STRIDE + bn] = __float_as_uint(rb.y);
        Bs[buf][(bq * 4 + 2) * BS_STRIDE + bn] = __float_as_uint(rb.z);
        Bs[buf][(bq * 4 + 3) * BS_STRIDE + bn] = __float_as_uint(rb.w);
        __syncthreads();

        if (it + 1 < NITER) loadAB(it + 1);

#pragma unroll
        for (int kk = 0; kk < 2; kk++) {
            const int kf = kk * 8 + (lane & 3);
            unsigned afr[2][4];
#pragma unroll
            for (int mt = 0; mt < 2; mt++) {
                int m = warp_m * 32 + mt * 16 + (lane >> 2);
                afr[mt][0] = As[buf][kf * AS_STRIDE + m];
                afr[mt][1] = As[buf][kf * AS_STRIDE + m + 8];
                afr[mt][2] = As[buf][(kf + 4) * AS_STRIDE + m];
                afr[mt][3] = As[buf][(kf + 4) * AS_STRIDE + m + 8];
            }
            unsigned bfr[4][2];
#pragma unroll
            for (int nt = 0; nt < 4; nt++) {
                int n = warp_n * 32 + nt * 8 + (lane >> 2);
                bfr[nt][0] = Bs[buf][kf * BS_STRIDE + n];
                bfr[nt][1] = Bs[buf][(kf + 4) * BS_STRIDE + n];
            }
#pragma unroll
            for (int mt = 0; mt < 2; mt++)
#pragma unroll
                for (int nt = 0; nt < 4; nt++)
                    mma_tf32(acc[mt][nt], afr[mt], bfr[nt]);
        }
    }

#pragma unroll
    for (int nt = 0; nt < 4; nt++) {
        int col = n0 + warp_n * 32 + nt * 8 + (lane & 3) * 2;   // permuted
        if (col >= GG) continue;
        int o0 = (col & 3) * 100 + (col >> 2);
        int o1 = ((col + 1) & 3) * 100 + ((col + 1) >> 2);
        float ba = b_ih[o0] + b_hh[o0];
        float bb = b_ih[o1] + b_hh[o1];
#pragma unroll
        for (int mt = 0; mt < 2; mt++) {
            int row0 = m0 + warp_m * 32 + mt * 16 + (lane >> 2);
            if (row0 < VV) {
                float2 v = make_float2(acc[mt][nt][0] + ba, acc[mt][nt][1] + bb);
                *reinterpret_cast<float2*>(&g_P[(size_t)row0 * GG + col]) = v;
            }
            int row1 = row0 + 8;
            if (row1 < VV) {
                float2 v = make_float2(acc[mt][nt][2] + ba, acc[mt][nt][3] + bb);
                *reinterpret_cast<float2*>(&g_P[(size_t)row1 * GG + col]) = v;
            }
        }
    }
}

// ---------------------------------------------------------------------------
// Kernel 2: label_vec[b] = emb[label_word_id[b]] @ ll_W^T + ll_b
// ---------------------------------------------------------------------------
__global__ void label_kernel(const int* __restrict__ label_word_id,
                             const float* __restrict__ emb,
                             const float* __restrict__ ll_W,
                             const float* __restrict__ ll_b) {
    __shared__ float row[EE];
    const int b = blockIdx.x;
    const int w = label_word_id[b];
    for (int e = threadIdx.x; e < EE; e += blockDim.x) row[e] = emb[w * EE + e];
    __syncthreads();
    const int j = threadIdx.x;
    if (j < HH) {
        float s = ll_b[j];
        const float* wr = &ll_W[j * EE];
        for (int e = 0; e < EE; e++) s += row[e] * wr[e];
        g_label[b * HH + j] = s;
    }
}

__global__ void probe_kernel() {
    if (threadIdx.x == 0) g_probe = 0.f;
}

// ---------------------------------------------------------------------------
// Kernel 3: LSTM recurrence. 128 CTAs x NB=8, 576 threads (18 warps).
//  - W_hh fragments register-resident; h streams via smem fragments
//  - P rows staged cooperatively (coalesced LDG, double-buffered smem;
//    LDG early, STS after mma -> latency hidden)
//  - g_out writes staged through smem, flushed coalesced one step behind
//  - ONE __syncthreads per step.
// ---------------------------------------------------------------------------
__global__ void __launch_bounds__(LSTM_THREADS, 1)
lstm_kernel(const int* __restrict__ word_id,
            const int* __restrict__ sen_len,
            const float* __restrict__ W_hh) {
    __shared__ unsigned Hf[2][KTILES * 64];
    __shared__ float Pbuf[2][NB * PB_STRIDE];
    __shared__ float Hout[2][NB * HO_STRIDE];
    __shared__ int senl[NB];

    const int tid = threadIdx.x;
    const int b0 = blockIdx.x * NB;
    const int lane = tid & 31;
    const int w = tid >> 5;
    const int nb = lane >> 2;
    const int cl2 = 2 * (lane & 3);

    // warps {12,13,16,17} get 2 tiles, rest 3 (SMSP-balanced: 13/13/12/12)
    const int ntc = (w == 12 || w == 13 || w == 16 || w == 17) ? 2 : 3;
    const int base = 3 * w - (w > 12) - (w > 13) - (w > 16) - (w > 17);

    // staging indices (P: 800 float4 ops in 2 rounds; Hout: 200 float4 ops)
    const int p_i0 = tid;            // < 800 ?
    const int p_i1 = tid + LSTM_THREADS;
    const int ho_nb = tid / 25;      // valid when tid < 200
    const int ho_j4 = (tid % 25) * 4;

    // ---- one-time: W_hh B-fragments into registers (permuted cols) ----
    unsigned Breg[3][KTILES][2];
#pragma unroll
    for (int i = 0; i < 3; i++) {
        int nt = base + i;
        int n_perm = nt * 8 + (lane >> 2);
        int orig_n = (n_perm & 3) * 100 + (n_perm >> 2);
        const float* wr = &W_hh[orig_n * HH];
#pragma unroll
        for (int kt = 0; kt < KTILES; kt++) {
            if (i < ntc) {
                int k0 = kt * 8 + (lane & 3);
                int k1 = k0 + 4;
                Breg[i][kt][0] = (k0 < HH) ? f2tf32(wr[k0]) : 0u;
                Breg[i][kt][1] = (k1 < HH) ? f2tf32(wr[k1]) : 0u;
            } else {
                Breg[i][kt][0] = 0u;
                Breg[i][kt][1] = 0u;
            }
        }
    }

    for (int idx = tid; idx < KTILES * 64; idx += LSTM_THREADS) Hf[0][idx] = 0u;
    if (tid < NB) senl[tid] = sen_len[b0 + tid];

    // prologue: stage P for t=0 into Pbuf[0]
#pragma unroll
    for (int r = 0; r < 2; r++) {
        int i = (r == 0) ? p_i0 : p_i1;
        if (i < NB * 100) {
            int pnb = i / 100, g4 = (i % 100) * 4;
            int wd = word_id[(b0 + pnb) * TT];
            float4 v = *reinterpret_cast<const float4*>(&g_P[(size_t)wd * GG + g4]);
            *reinterpret_cast<float4*>(&Pbuf[0][pnb * PB_STRIDE + g4]) = v;
        }
    }
    __syncthreads();

    float cst[2] = {0.f, 0.f};

    for (int t = 0; t < TT; t++) {
        const int buf = t & 1;

        // 1. issue LDGs for P(t+1) into regs (STS deferred past mma)
        float4 rp0, rp1;
        bool p0v = false, p1v = false;
        if (t + 1 < TT) {
            if (p_i0 < NB * 100) {
                int pnb = p_i0 / 100, g4 = (p_i0 % 100) * 4;
                int wd = word_id[(b0 + pnb) * TT + t + 1];
                rp0 = *reinterpret_cast<const float4*>(&g_P[(size_t)wd * GG + g4]);
                p0v = true;
            }
            if (p_i1 < NB * 100) {
                int pnb = p_i1 / 100, g4 = (p_i1 % 100) * 4;
                int wd = word_id[(b0 + pnb) * TT + t + 1];
                rp1 = *reinterpret_cast<const float4*>(&g_P[(size_t)wd * GG + g4]);
                p1v = true;
            }
        }

        // 2. flush h(t-1) from Hout -> g_out (coalesced float4)
        if (t > 0 && tid < 200) {
            float4 v = *reinterpret_cast<const float4*>(
                &Hout[1 - buf][ho_nb * HO_STRIDE + ho_j4]);
            *reinterpret_cast<float4*>(
                &g_out[((size_t)(b0 + ho_nb) * TT + (t - 1)) * HH + ho_j4]) = v;
        }

        // 3. mma: gates = h @ WhhT + P
        float2 pv[3];
#pragma unroll
        for (int i = 0; i < 3; i++) {
            if (i < ntc)
                pv[i] = *reinterpret_cast<const float2*>(
                    &Pbuf[buf][nb * PB_STRIDE + (base + i) * 8 + cl2]);
        }

        float acc[3][4];
#pragma unroll
        for (int i = 0; i < 3; i++) {
            acc[i][0] = 0.f; acc[i][1] = 0.f; acc[i][2] = 0.f; acc[i][3] = 0.f;
        }
#pragma unroll
        for (int kt = 0; kt < KTILES; kt++) {
            uint2 hv = *reinterpret_cast<const uint2*>(&Hf[buf][(kt * 32 + lane) * 2]);
#pragma unroll
            for (int i = 0; i < 3; i++) {
                if (i < ntc)
                    mma_tf32_half4(acc[i], hv.x, hv.y, Breg[i][kt][0], Breg[i][kt][1]);
            }
        }
#pragma unroll
        for (int i = 0; i < 3; i++) {
            if (i < ntc) { acc[i][0] += pv[i].x; acc[i][1] += pv[i].y; }
        }

        // 4. STS deferred P stage (LDG latency now hidden under the mma work)
        if (p0v) {
            int pnb = p_i0 / 100, g4 = (p_i0 % 100) * 4;
            *reinterpret_cast<float4*>(&Pbuf[1 - buf][pnb * PB_STRIDE + g4]) = rp0;
        }
        if (p1v) {
            int pnb = p_i1 / 100, g4 = (p_i1 % 100) * 4;
            *reinterpret_cast<float4*>(&Pbuf[1 - buf][pnb * PB_STRIDE + g4]) = rp1;
        }

        // 5. activation: bundles (tiles 0,1) then (2,2)
        const bool odd = (lane & 1);
        const int jsel = (lane >> 1) & 1;
#pragma unroll
        for (int bundle = 0; bundle < 2; bundle++) {
            if (bundle == 1 && ntc < 3) break;
            const int iA = (bundle == 0) ? 0 : 2;
            const int iB = (bundle == 0) ? 1 : 2;
            float xA0 = __shfl_xor_sync(0xffffffffu, acc[iA][0], 1);
            float xA1 = __shfl_xor_sync(0xffffffffu, acc[iA][1], 1);
            float xB0 = __shfl_xor_sync(0xffffffffu, acc[iB][0], 1);
            float xB1 = __shfl_xor_sync(0xffffffffu, acc[iB][1], 1);
            float gi = odd ? xB0 : acc[iA][0];
            float gf = odd ? xB1 : acc[iA][1];
            float gg = odd ? acc[iB][0] : xA0;
            float go = odd ? acc[iB][1] : xA1;
            int nt = base + (odd ? iB : iA);
            int j = 2 * nt + jsel;

            float si = sigm_hw(gi);
            float sf = sigm_hw(gf);
            float so = sigm_hw(go);
            float sg = tanh_hw(gg);
            float cv = sf * cst[bundle] + si * sg;
            cst[bundle] = cv;
            float h = so * tanh_hw(cv);

            if (!(iA == iB && odd)) {
                int jl = j & 7, kt = j >> 3;
                Hf[1 - buf][(kt * 32 + ((nb << 2) | (jl & 3))) * 2 + ((jl >> 2) & 1)]
                    = f2tf32(h);
                Hout[buf][nb * HO_STRIDE + j] = h;
                if (t == senl[nb] - 1) g_last[(b0 + nb) * HH + j] = h;
            }
        }
        __syncthreads();
    }

    // flush final step's h (t = TT-1 lives in Hout[(TT-1)&1])
    if (tid < 200) {
        float4 v = *reinterpret_cast<const float4*>(
            &Hout[(TT - 1) & 1][ho_nb * HO_STRIDE + ho_j4]);
        *reinterpret_cast<float4*>(
            &g_out[((size_t)(b0 + ho_nb) * TT + (TT - 1)) * HH + ho_j4]) = v;
    }
}

// ---------------------------------------------------------------------------
// Kernel 4: per-batch epilogue: scores, top-4, pos, per_neg, out_f, l_rep, q.
// ---------------------------------------------------------------------------
__global__ void catch_kernel(const int* __restrict__ sen_len,
                             const float* __restrict__ lin_W,
                             const float* __restrict__ lin_b,
                             float* __restrict__ dout) {
    __shared__ float label_s[HH];
    __shared__ float last_s[HH];
    __shared__ float scores[TT];
    __shared__ float red_v[TT];
    __shared__ int   red_i[TT];
    __shared__ float topv[4];
    __shared__ int   topi[4];
    __shared__ float pos_s[HH];
    __shared__ float pneg_s[HH];

    const int b = blockIdx.x;
    const int tid = threadIdx.x;
    const int L = sen_len[b];

    if (tid < HH) {
        label_s[tid] = g_label[b * HH + tid];
        last_s[tid]  = g_last[b * HH + tid];
    }
    __syncthreads();

    {
        float s;
        if (tid < L) {
            s = 0.f;
            const float* o = &g_out[((size_t)b * TT + tid) * HH];
            for (int j = 0; j < HH; j++) s += o[j] * label_s[j];
        } else {
            s = -1e30f;
        }
        scores[tid] = s;
    }
    __syncthreads();

    for (int k = 0; k < 4; k++) {
        red_v[tid] = scores[tid];
        red_i[tid] = tid;
        __syncthreads();
        for (int off = TT / 2; off > 0; off >>= 1) {
            if (tid < off) {
                float v2 = red_v[tid + off];
                int   i2 = red_i[tid + off];
                if (v2 > red_v[tid] || (v2 == red_v[tid] && i2 < red_i[tid])) {
                    red_v[tid] = v2;
                    red_i[tid] = i2;
                }
            }
            __syncthreads();
        }
        if (tid == 0) {
            topv[k] = red_v[0];
            topi[k] = red_i[0];
            scores[red_i[0]] = -1e30f;
        }
        __syncthreads();
    }

    if (tid < HH) {
        float p = 0.f;
#pragma unroll
        for (int k = 0; k < 4; k++)
            p += g_out[((size_t)b * TT + topi[k]) * HH + tid] * topv[k];
        pos_s[tid] = p;

        float s = 0.f;
        int i0 = topi[0], i1 = topi[1], i2 = topi[2], i3 = topi[3];
        for (int t = 0; t < L; t++) {
            if (t == i0 || t == i1 || t == i2 || t == i3) continue;
            s += g_out[((size_t)b * TT + t) * HH + tid];
        }
        pneg_s[tid] = s;
    }
    __syncthreads();

    if (tid < 6) {
        float bo = lin_b[tid];
        float o = bo, l = bo, q = 0.f;
        const float* wv = &lin_W[tid * HH];
        for (int j = 0; j < HH; j++) {
            float wj = wv[j];
            o += last_s[j] * wj;
            l += pos_s[j] * wj;
            q += pneg_s[j] * wj;
        }
        dout[b * 6 + tid] = o;
        dout[BB * 6 + b * 6 + tid] = l;
        g_q[b * 6 + tid] = q;
    }
}

// ---------------------------------------------------------------------------
// Kernel 5: r_rep = cumsum over batch of q + lin_b (warp-parallel scan).
// ---------------------------------------------------------------------------
__global__ void scan_kernel(const float* __restrict__ lin_b,
                            float* __restrict__ dout) {
    const int w = threadIdx.x >> 5;
    const int l = threadIdx.x & 31;
    if (w >= 6) return;
    float run = lin_b[w];
    for (int c0 = 0; c0 < BB; c0 += 32) {
        float v = g_q[(c0 + l) * 6 + w];
#pragma unroll
        for (int off = 1; off < 32; off <<= 1) {
            float u = __shfl_up_sync(0xffffffff, v, off);
            if (l >= off) v += u;
        }
        dout[2 * BB * 6 + (c0 + l) * 6 + w] = run + v;
        run += __shfl_sync(0xffffffff, v, 31);
    }
}

// ---------------------------------------------------------------------------
extern "C" void kernel_launch(void* const* d_in, const int* in_sizes, int n_in,
                              void* d_out, int out_size) {
    const int*   word_id       = (const int*)d_in[0];
    const int*   sen_len       = (const int*)d_in[1];
    const int*   label_word_id = (const int*)d_in[2];
    const float* emb           = (const float*)d_in[3];
    const float* W_ih          = (const float*)d_in[4];
    const float* W_hh          = (const float*)d_in[5];
    const float* b_ih          = (const float*)d_in[6];
    const float* b_hh          = (const float*)d_in[7];
    const float* lin_W         = (const float*)d_in[8];
    const float* lin_b         = (const float*)d_in[9];
    const float* ll_W          = (const float*)d_in[10];
    const float* ll_b          = (const float*)d_in[11];
    float* out = (float*)d_out;

    dim3 ggrid((GG + 63) / 64, (VV + 127) / 128);   // n fastest -> A slab L2 reuse
    gemm_P_kernel<<<ggrid, 256>>>(emb, W_ih, b_ih, b_hh);            // idx 0
    label_kernel<<<BB, 128>>>(label_word_id, emb, ll_W, ll_b);       // idx 1
    probe_kernel<<<1, 32>>>();                                       // idx 2 (shifts ncu slot)
    lstm_kernel<<<BB / NB, LSTM_THREADS>>>(word_id, sen_len, W_hh);  // idx 3
    catch_kernel<<<BB, 128>>>(sen_len, lin_W, lin_b, out);           // idx 4
    scan_kernel<<<1, 192>>>(lin_b, out);                             // idx 5
}

// round 9
// speedup vs baseline: 1.2574x; 1.2574x over previous
#include <cuda_runtime.h>
#include <cuda_bf16.h>
#include <math.h>

// Problem dims
#define BB 1024
#define TT 128
#define EE 300
#define HH 100
#define GG 400     // 4*H
#define VV 50000
#define NB 8       // batches per LSTM CTA
#define NTILES 50  // GG/8 (permuted gate-interleaved layout)
#define KTILES 13  // ceil(HH/8)
#define LSTM_THREADS 576

// Scratch (device globals -- no allocation allowed)
// g_P is stored COLUMN-PERMUTED: permuted col p holds orig col (p&3)*100+(p>>2)
__device__ float g_P[VV * GG];
__device__ float g_out[BB * TT * HH]; // hidden states (52 MB)
__device__ float g_last[BB * HH];
__device__ float g_label[BB * HH];
__device__ float g_q[BB * 6];
__device__ float g_probe;

// ---------------- PTX helpers ----------------
__device__ __forceinline__ unsigned f2tf32(float x) {
    unsigned u;
    asm("cvt.rna.tf32.f32 %0, %1;" : "=r"(u) : "f"(x));
    return u;
}

__device__ __forceinline__ void mma_tf32(float* d, const unsigned* a, const unsigned* b) {
    asm volatile(
        "mma.sync.aligned.m16n8k8.row.col.f32.tf32.tf32.f32 "
        "{%0,%1,%2,%3}, {%4,%5,%6,%7}, {%8,%9}, {%0,%1,%2,%3};"
        : "+f"(d[0]), "+f"(d[1]), "+f"(d[2]), "+f"(d[3])
        : "r"(a[0]), "r"(a[1]), "r"(a[2]), "r"(a[3]), "r"(b[0]), "r"(b[1]));
}

// Rows 8..15 of A are zero padding -> a1,a3 = 0. d[2],d[3] are per-tile junk
// slots (MUST be per-tile: sharing them across tiles serializes the HMMA chain).
__device__ __forceinline__ void mma_tf32_half4(float* d, unsigned a0, unsigned a2,
                                               unsigned b0, unsigned b1) {
    asm volatile(
        "mma.sync.aligned.m16n8k8.row.col.f32.tf32.tf32.f32 "
        "{%0,%1,%2,%3}, {%4,%5,%6,%7}, {%8,%9}, {%0,%1,%2,%3};"
        : "+f"(d[0]), "+f"(d[1]), "+f"(d[2]), "+f"(d[3])
        : "r"(a0), "r"(0u), "r"(a2), "r"(0u), "r"(b0), "r"(b1));
}

// HW tanh (sm_75+): single MUFU op, ~2^-11 abs error
__device__ __forceinline__ float tanh_hw(float x) {
    float y;
    asm("tanh.approx.f32 %0, %1;" : "=f"(y) : "f"(x));
    return y;
}
__device__ __forceinline__ float sigm_hw(float x) {
    return fmaf(tanh_hw(0.5f * x), 0.5f, 0.5f);
}

// ---------------------------------------------------------------------------
// Kernel 1: P[v, p] = sum_e emb[v,e]*W_ih[orig(p),e] + bias[orig(p)]
// Permutation applied at B-LOAD time -> epilogue stores are contiguous.
// tf32 mma GEMM, 128x64 CTA tile, BK=16, double-buffered smem + reg prefetch.
// ---------------------------------------------------------------------------
#define AS_STRIDE 132
#define BS_STRIDE 68
#define NITER 19   // ceil(300/16)

__global__ void gemm_P_kernel(const float* __restrict__ emb,
                              const float* __restrict__ W_ih,
                              const float* __restrict__ b_ih,
                              const float* __restrict__ b_hh) {
    __shared__ unsigned As[2][16 * AS_STRIDE];
    __shared__ unsigned Bs[2][16 * BS_STRIDE];

    const int m0 = blockIdx.y * 128;
    const int n0 = blockIdx.x * 64;   // permuted-column block
    const int tid = threadIdx.x;
    const int lane = tid & 31;
    const int wid = tid >> 5;
    const int warp_m = wid & 3;
    const int warp_n = wid >> 2;

    float acc[2][4][4];
#pragma unroll
    for (int mt = 0; mt < 2; mt++)
#pragma unroll
        for (int nt = 0; nt < 4; nt++)
#pragma unroll
            for (int c = 0; c < 4; c++) acc[mt][nt][c] = 0.f;

    float4 ra[2], rb;
    const int aq = tid & 3;
    const int am0 = (tid >> 2);
    const int bq = tid & 3;
    const int bn = tid >> 2;
    const int gn_p = n0 + bn;
    const int gn_orig = (gn_p & 3) * 100 + (gn_p >> 2);

    auto loadAB = [&](int it) {
        int k0 = it * 16;
#pragma unroll
        for (int i = 0; i < 2; i++) {
            int m = am0 + i * 64;
            int gm = m0 + m;
            int gk = k0 + aq * 4;
            ra[i] = make_float4(0.f, 0.f, 0.f, 0.f);
            if (gm < VV && gk < EE)
                ra[i] = *reinterpret_cast<const float4*>(&emb[gm * EE + gk]);
        }
        int gk = k0 + bq * 4;
        rb = make_float4(0.f, 0.f, 0.f, 0.f);
        if (gn_p < GG && gk < EE)
            rb = *reinterpret_cast<const float4*>(&W_ih[gn_orig * EE + gk]);
    };

    loadAB(0);

    for (int it = 0; it < NITER; it++) {
        const int buf = it & 1;
#pragma unroll
        for (int i = 0; i < 2; i++) {
            int m = am0 + i * 64;
            As[buf][(aq * 4 + 0) * AS_STRIDE + m] = __float_as_uint(ra[i].x);
            As[buf][(aq * 4 + 1) * AS_STRIDE + m] = __float_as_uint(ra[i].y);
            As[buf][(aq * 4 + 2) * AS_STRIDE + m] = __float_as_uint(ra[i].z);
            As[buf][(aq * 4 + 3) * AS_STRIDE + m] = __float_as_uint(ra[i].w);
        }
        Bs[buf][(bq * 4 + 0) * BS_STRIDE + bn] = __float_as_uint(rb.x);
        Bs[buf][(bq * 4 + 1) * BS_STRIDE + bn] = __float_as_uint(rb.y);
        Bs[buf][(bq * 4 + 2) * BS_STRIDE + bn] = __float_as_uint(rb.z);
        Bs[buf][(bq * 4 + 3) * BS_STRIDE + bn] = __float_as_uint(rb.w);
        __syncthreads();

        if (it + 1 < NITER) loadAB(it + 1);

#pragma unroll
        for (int kk = 0; kk < 2; kk++) {
            const int kf = kk * 8 + (lane & 3);
            unsigned afr[2][4];
#pragma unroll
            for (int mt = 0; mt < 2; mt++) {
                int m = warp_m * 32 + mt * 16 + (lane >> 2);
                afr[mt][0] = As[buf][kf * AS_STRIDE + m];
                afr[mt][1] = As[buf][kf * AS_STRIDE + m + 8];
                afr[mt][2] = As[buf][(kf + 4) * AS_STRIDE + m];
                afr[mt][3] = As[buf][(kf + 4) * AS_STRIDE + m + 8];
            }
            unsigned bfr[4][2];
#pragma unroll
            for (int nt = 0; nt < 4; nt++) {
                int n = warp_n * 32 + nt * 8 + (lane >> 2);
                bfr[nt][0] = Bs[buf][kf * BS_STRIDE + n];
                bfr[nt][1] = Bs[buf][(kf + 4) * BS_STRIDE + n];
            }
#pragma unroll
            for (int mt = 0; mt < 2; mt++)
#pragma unroll
                for (int nt = 0; nt < 4; nt++)
                    mma_tf32(acc[mt][nt], afr[mt], bfr[nt]);
        }
    }

#pragma unroll
    for (int nt = 0; nt < 4; nt++) {
        int col = n0 + warp_n * 32 + nt * 8 + (lane & 3) * 2;   // permuted
        if (col >= GG) continue;
        int o0 = (col & 3) * 100 + (col >> 2);
        int o1 = ((col + 1) & 3) * 100 + ((col + 1) >> 2);
        float ba = b_ih[o0] + b_hh[o0];
        float bb = b_ih[o1] + b_hh[o1];
#pragma unroll
        for (int mt = 0; mt < 2; mt++) {
            int row0 = m0 + warp_m * 32 + mt * 16 + (lane >> 2);
            if (row0 < VV) {
                float2 v = make_float2(acc[mt][nt][0] + ba, acc[mt][nt][1] + bb);
                *reinterpret_cast<float2*>(&g_P[(size_t)row0 * GG + col]) = v;
            }
            int row1 = row0 + 8;
            if (row1 < VV) {
                float2 v = make_float2(acc[mt][nt][2] + ba, acc[mt][nt][3] + bb);
                *reinterpret_cast<float2*>(&g_P[(size_t)row1 * GG + col]) = v;
            }
        }
    }
}

// ---------------------------------------------------------------------------
// Kernel 2: label_vec[b] = emb[label_word_id[b]] @ ll_W^T + ll_b
// ---------------------------------------------------------------------------
__global__ void label_kernel(const int* __restrict__ label_word_id,
                             const float* __restrict__ emb,
                             const float* __restrict__ ll_W,
                             const float* __restrict__ ll_b) {
    __shared__ float row[EE];
    const int b = blockIdx.x;
    const int w = label_word_id[b];
    for (int e = threadIdx.x; e < EE; e += blockDim.x) row[e] = emb[w * EE + e];
    __syncthreads();
    const int j = threadIdx.x;
    if (j < HH) {
        float s = ll_b[j];
        const float* wr = &ll_W[j * EE];
        for (int e = 0; e < EE; e++) s += row[e] * wr[e];
        g_label[b * HH + j] = s;
    }
}

__global__ void probe_kernel() {
    if (threadIdx.x == 0) g_probe = 0.f;
}

// ---------------------------------------------------------------------------
// Kernel 3: LSTM recurrence. 128 CTAs x NB=8, 576 threads (18 warps).
// R5 structure (best measured) with the register-spill fix:
//  - W_hh fragments for each warp's tiles 0,1 live in REGISTERS (52 regs)
//  - each warp's 3rd tile (if any) streams from smem Bs3 (conflict-free LDS.64)
//    -> total live regs ~87 < 96 cap, no LDL/STL spills
//  - only h streams through smem fragments; ONE __syncthreads per step.
// ---------------------------------------------------------------------------
__global__ void __launch_bounds__(LSTM_THREADS, 1)
lstm_kernel(const int* __restrict__ word_id,
            const int* __restrict__ sen_len,
            const float* __restrict__ W_hh) {
    __shared__ unsigned Hf[2][KTILES * 64];
    __shared__ unsigned Bs3[14 * KTILES * 64];   // 3rd-tile B frags for 14 warps
    __shared__ int rows[2][NB];
    __shared__ int senl[NB];

    const int tid = threadIdx.x;
    const int b0 = blockIdx.x * NB;
    const int lane = tid & 31;
    const int w = tid >> 5;
    const int nb = lane >> 2;
    const int cl2 = 2 * (lane & 3);

    // warps {12,13,16,17} get 2 tiles, rest 3 (SMSP-balanced: 13/13/12/12)
    const int ntc = (w == 12 || w == 13 || w == 16 || w == 17) ? 2 : 3;
    const int base = 3 * w - (w > 12) - (w > 13) - (w > 16) - (w > 17);
    // smem slot for 3-tile warps: {0..11,14,15} -> {0..11,12,13}
    const int slot3 = (w < 12) ? w : w - 2;
    const unsigned* Bs3w = &Bs3[slot3 * KTILES * 64];

    // ---- one-time: tiles 0,1 B-fragments into registers (permuted cols) ----
    unsigned Breg[2][KTILES][2];
#pragma unroll
    for (int i = 0; i < 2; i++) {
        int nt = base + i;
        int n_perm = nt * 8 + (lane >> 2);
        int orig_n = (n_perm & 3) * 100 + (n_perm >> 2);
        const float* wr = &W_hh[orig_n * HH];
#pragma unroll
        for (int kt = 0; kt < KTILES; kt++) {
            int k0 = kt * 8 + (lane & 3);
            int k1 = k0 + 4;
            Breg[i][kt][0] = (k0 < HH) ? f2tf32(wr[k0]) : 0u;
            Breg[i][kt][1] = (k1 < HH) ? f2tf32(wr[k1]) : 0u;
        }
    }
    // ---- one-time: 3rd tile B-fragments into smem ----
    if (ntc == 3) {
        int nt = base + 2;
        int n_perm = nt * 8 + (lane >> 2);
        int orig_n = (n_perm & 3) * 100 + (n_perm >> 2);
        const float* wr = &W_hh[orig_n * HH];
        for (int kt = 0; kt < KTILES; kt++) {
            int k0 = kt * 8 + (lane & 3);
            int k1 = k0 + 4;
            unsigned v0 = (k0 < HH) ? f2tf32(wr[k0]) : 0u;
            unsigned v1 = (k1 < HH) ? f2tf32(wr[k1]) : 0u;
            Bs3[slot3 * KTILES * 64 + kt * 64 + lane * 2]     = v0;
            Bs3[slot3 * KTILES * 64 + kt * 64 + lane * 2 + 1] = v1;
        }
    }

    for (int idx = tid; idx < KTILES * 64; idx += LSTM_THREADS) Hf[0][idx] = 0u;
    if (tid < NB) {
        senl[tid] = sen_len[b0 + tid];
        rows[0][tid] = word_id[(b0 + tid) * TT];
    }
    __syncthreads();

    float cst[2] = {0.f, 0.f};

    for (int t = 0; t < TT; t++) {
        const int buf = t & 1;

        // prefetch P rows (permuted, tile-aligned)
        float2 pv[3];
        {
            const float* Prow = &g_P[(size_t)rows[buf][nb] * GG];
            pv[0] = *reinterpret_cast<const float2*>(&Prow[(base + 0) * 8 + cl2]);
            pv[1] = *reinterpret_cast<const float2*>(&Prow[(base + 1) * 8 + cl2]);
            if (ntc == 3)
                pv[2] = *reinterpret_cast<const float2*>(&Prow[(base + 2) * 8 + cl2]);
        }

        float acc[3][4];   // per-tile: d0,d1 real, d2,d3 junk (independent chains)
#pragma unroll
        for (int i = 0; i < 3; i++) {
            acc[i][0] = 0.f; acc[i][1] = 0.f; acc[i][2] = 0.f; acc[i][3] = 0.f;
        }

#pragma unroll
        for (int kt = 0; kt < KTILES; kt++) {
            uint2 hv = *reinterpret_cast<const uint2*>(&Hf[buf][(kt * 32 + lane) * 2]);
            mma_tf32_half4(acc[0], hv.x, hv.y, Breg[0][kt][0], Breg[0][kt][1]);
            mma_tf32_half4(acc[1], hv.x, hv.y, Breg[1][kt][0], Breg[1][kt][1]);
            if (ntc == 3) {
                uint2 bv = *reinterpret_cast<const uint2*>(&Bs3w[kt * 64 + lane * 2]);
                mma_tf32_half4(acc[2], hv.x, hv.y, bv.x, bv.y);
            }
        }
        acc[0][0] += pv[0].x; acc[0][1] += pv[0].y;
        acc[1][0] += pv[1].x; acc[1][1] += pv[1].y;
        if (ntc == 3) { acc[2][0] += pv[2].x; acc[2][1] += pv[2].y; }

        // ---- merged activation: bundles (tiles 0,1) then (2,2) ----
        const bool odd = (lane & 1);
        const int jsel = (lane >> 1) & 1;
#pragma unroll
        for (int bundle = 0; bundle < 2; bundle++) {
            if (bundle == 1 && ntc < 3) break;
            const int iA = (bundle == 0) ? 0 : 2;
            const int iB = (bundle == 0) ? 1 : 2;
            float xA0 = __shfl_xor_sync(0xffffffffu, acc[iA][0], 1);
            float xA1 = __shfl_xor_sync(0xffffffffu, acc[iA][1], 1);
            float xB0 = __shfl_xor_sync(0xffffffffu, acc[iB][0], 1);
            float xB1 = __shfl_xor_sync(0xffffffffu, acc[iB][1], 1);
            float gi = odd ? xB0 : acc[iA][0];
            float gf = odd ? xB1 : acc[iA][1];
            float gg = odd ? acc[iB][0] : xA0;
            float go = odd ? acc[iB][1] : xA1;
            int nt = base + (odd ? iB : iA);
            int j = 2 * nt + jsel;

            float si = sigm_hw(gi);
            float sf = sigm_hw(gf);
            float so = sigm_hw(go);
            float sg = tanh_hw(gg);
            float cv = sf * cst[bundle] + si * sg;
            cst[bundle] = cv;
            float h = so * tanh_hw(cv);

            if (!(iA == iB && odd)) {
                int jl = j & 7, kt = j >> 3;
                Hf[1 - buf][(kt * 32 + ((nb << 2) | (jl & 3))) * 2 + ((jl >> 2) & 1)]
                    = f2tf32(h);
                g_out[((size_t)(b0 + nb) * TT + t) * HH + j] = h;
                if (t == senl[nb] - 1) g_last[(b0 + nb) * HH + j] = h;
            }
        }

        if (tid < NB && t + 1 < TT)
            rows[1 - buf][tid] = word_id[(b0 + tid) * TT + t + 1];
        __syncthreads();
    }
}

// ---------------------------------------------------------------------------
// Kernel 4: per-batch epilogue: scores, top-4, pos, per_neg, out_f, l_rep, q.
// ---------------------------------------------------------------------------
__global__ void catch_kernel(const int* __restrict__ sen_len,
                             const float* __restrict__ lin_W,
                             const float* __restrict__ lin_b,
                             float* __restrict__ dout) {
    __shared__ float label_s[HH];
    __shared__ float last_s[HH];
    __shared__ float scores[TT];
    __shared__ float red_v[TT];
    __shared__ int   red_i[TT];
    __shared__ float topv[4];
    __shared__ int   topi[4];
    __shared__ float pos_s[HH];
    __shared__ float pneg_s[HH];

    const int b = blockIdx.x;
    const int tid = threadIdx.x;
    const int L = sen_len[b];

    if (tid < HH) {
        label_s[tid] = g_label[b * HH + tid];
        last_s[tid]  = g_last[b * HH + tid];
    }
    __syncthreads();

    {
        float s;
        if (tid < L) {
            s = 0.f;
            const float* o = &g_out[((size_t)b * TT + tid) * HH];
            for (int j = 0; j < HH; j++) s += o[j] * label_s[j];
        } else {
            s = -1e30f;
        }
        scores[tid] = s;
    }
    __syncthreads();

    for (int k = 0; k < 4; k++) {
        red_v[tid] = scores[tid];
        red_i[tid] = tid;
        __syncthreads();
        for (int off = TT / 2; off > 0; off >>= 1) {
            if (tid < off) {
                float v2 = red_v[tid + off];
                int   i2 = red_i[tid + off];
                if (v2 > red_v[tid] || (v2 == red_v[tid] && i2 < red_i[tid])) {
                    red_v[tid] = v2;
                    red_i[tid] = i2;
                }
            }
            __syncthreads();
        }
        if (tid == 0) {
            topv[k] = red_v[0];
            topi[k] = red_i[0];
            scores[red_i[0]] = -1e30f;
        }
        __syncthreads();
    }

    if (tid < HH) {
        float p = 0.f;
#pragma unroll
        for (int k = 0; k < 4; k++)
            p += g_out[((size_t)b * TT + topi[k]) * HH + tid] * topv[k];
        pos_s[tid] = p;

        float s = 0.f;
        int i0 = topi[0], i1 = topi[1], i2 = topi[2], i3 = topi[3];
        for (int t = 0; t < L; t++) {
            if (t == i0 || t == i1 || t == i2 || t == i3) continue;
            s += g_out[((size_t)b * TT + t) * HH + tid];
        }
        pneg_s[tid] = s;
    }
    __syncthreads();

    if (tid < 6) {
        float bo = lin_b[tid];
        float o = bo, l = bo, q = 0.f;
        const float* wv = &lin_W[tid * HH];
        for (int j = 0; j < HH; j++) {
            float wj = wv[j];
            o += last_s[j] * wj;
            l += pos_s[j] * wj;
            q += pneg_s[j] * wj;
        }
        dout[b * 6 + tid] = o;
        dout[BB * 6 + b * 6 + tid] = l;
        g_q[b * 6 + tid] = q;
    }
}

// ---------------------------------------------------------------------------
// Kernel 5: r_rep = cumsum over batch of q + lin_b (warp-parallel scan).
// ---------------------------------------------------------------------------
__global__ void scan_kernel(const float* __restrict__ lin_b,
                            float* __restrict__ dout) {
    const int w = threadIdx.x >> 5;
    const int l = threadIdx.x & 31;
    if (w >= 6) return;
    float run = lin_b[w];
    for (int c0 = 0; c0 < BB; c0 += 32) {
        float v = g_q[(c0 + l) * 6 + w];
#pragma unroll
        for (int off = 1; off < 32; off <<= 1) {
            float u = __shfl_up_sync(0xffffffff, v, off);
            if (l >= off) v += u;
        }
        dout[2 * BB * 6 + (c0 + l) * 6 + w] = run + v;
        run += __shfl_sync(0xffffffff, v, 31);
    }
}

// ---------------------------------------------------------------------------
extern "C" void kernel_launch(void* const* d_in, const int* in_sizes, int n_in,
                              void* d_out, int out_size) {
    const int*   word_id       = (const int*)d_in[0];
    const int*   sen_len       = (const int*)d_in[1];
    const int*   label_word_id = (const int*)d_in[2];
    const float* emb           = (const float*)d_in[3];
    const float* W_ih          = (const float*)d_in[4];
    const float* W_hh          = (const float*)d_in[5];
    const float* b_ih          = (const float*)d_in[6];
    const float* b_hh          = (const float*)d_in[7];
    const float* lin_W         = (const float*)d_in[8];
    const float* lin_b         = (const float*)d_in[9];
    const float* ll_W          = (const float*)d_in[10];
    const float* ll_b          = (const float*)d_in[11];
    float* out = (float*)d_out;

    dim3 ggrid((GG + 63) / 64, (VV + 127) / 128);   // n fastest -> A slab L2 reuse
    // ncu captures launch index 3 -> place gemm_P there this round.
    probe_kernel<<<1, 32>>>();                                       // idx 0
    probe_kernel<<<1, 32>>>();                                       // idx 1
    probe_kernel<<<1, 32>>>();                                       // idx 2
    gemm_P_kernel<<<ggrid, 256>>>(emb, W_ih, b_ih, b_hh);            // idx 3 (profiled)
    label_kernel<<<BB, 128>>>(label_word_id, emb, ll_W, ll_b);       // idx 4
    lstm_kernel<<<BB / NB, LSTM_THREADS>>>(word_id, sen_len, W_hh);  // idx 5
    catch_kernel<<<BB, 128>>>(sen_len, lin_W, lin_b, out);           // idx 6
    scan_kernel<<<1, 192>>>(lin_b, out);                             // idx 7
}

// round 11
// speedup vs baseline: 1.3659x; 1.0863x over previous
#include <cuda_runtime.h>
#include <cuda_bf16.h>
#include <math.h>

// Problem dims
#define BB 1024
#define TT 128
#define EE 300
#define HH 100
#define GG 400     // 4*H
#define VV 50000
#define NB 8       // batches per LSTM CTA
#define NTILES 50  // GG/8 (permuted gate-interleaved layout)
#define KTILES 13  // ceil(HH/8)
#define LSTM_THREADS 576

// Scratch (device globals -- no allocation allowed)
// g_P is stored COLUMN-PERMUTED: permuted col p holds orig col (p&3)*100+(p>>2)
__device__ float g_P[VV * GG];
__device__ float g_out[BB * TT * HH]; // hidden states (52 MB)
__device__ float g_last[BB * HH];
__device__ float g_label[BB * HH];
__device__ float g_q[BB * 6];
__device__ float g_probe;

// ---------------- PTX helpers ----------------
__device__ __forceinline__ unsigned f2tf32(float x) {
    unsigned u;
    asm("cvt.rna.tf32.f32 %0, %1;" : "=r"(u) : "f"(x));
    return u;
}

__device__ __forceinline__ void mma_tf32(float* d, const unsigned* a, const unsigned* b) {
    asm volatile(
        "mma.sync.aligned.m16n8k8.row.col.f32.tf32.tf32.f32 "
        "{%0,%1,%2,%3}, {%4,%5,%6,%7}, {%8,%9}, {%0,%1,%2,%3};"
        : "+f"(d[0]), "+f"(d[1]), "+f"(d[2]), "+f"(d[3])
        : "r"(a[0]), "r"(a[1]), "r"(a[2]), "r"(a[3]), "r"(b[0]), "r"(b[1]));
}

// Rows 8..15 of A are zero padding -> a1,a3 = 0. d[2],d[3] are per-tile junk
// slots (MUST be per-tile: sharing them across tiles serializes the HMMA chain).
__device__ __forceinline__ void mma_tf32_half4(float* d, unsigned a0, unsigned a2,
                                               unsigned b0, unsigned b1) {
    asm volatile(
        "mma.sync.aligned.m16n8k8.row.col.f32.tf32.tf32.f32 "
        "{%0,%1,%2,%3}, {%4,%5,%6,%7}, {%8,%9}, {%0,%1,%2,%3};"
        : "+f"(d[0]), "+f"(d[1]), "+f"(d[2]), "+f"(d[3])
        : "r"(a0), "r"(0u), "r"(a2), "r"(0u), "r"(b0), "r"(b1));
}

// ldmatrix: an 8x8 tf32 tile stored as rows of 4 consecutive tf32 (16B) is
// bit-identical to 8x16 b16; m8n8.b16 distribution gives lane 4r+c element
// (r, c) as u32 -> exactly the tf32 mma fragment mapping.
__device__ __forceinline__ void ldsm_x4(unsigned* r, unsigned addr) {
    asm volatile("ldmatrix.sync.aligned.m8n8.x4.shared.b16 {%0,%1,%2,%3}, [%4];"
        : "=r"(r[0]), "=r"(r[1]), "=r"(r[2]), "=r"(r[3]) : "r"(addr));
}
__device__ __forceinline__ void ldsm_x2(unsigned* r, unsigned addr) {
    asm volatile("ldmatrix.sync.aligned.m8n8.x2.shared.b16 {%0,%1}, [%2];"
        : "=r"(r[0]), "=r"(r[1]) : "r"(addr));
}

// HW tanh (sm_75+): single MUFU op, ~2^-11 abs error
__device__ __forceinline__ float tanh_hw(float x) {
    float y;
    asm("tanh.approx.f32 %0, %1;" : "=f"(y) : "f"(x));
    return y;
}
__device__ __forceinline__ float sigm_hw(float x) {
    return fmaf(tanh_hw(0.5f * x), 0.5f, 0.5f);
}

// ---------------------------------------------------------------------------
// Kernel 1: P[v, p] = sum_e emb[v,e]*W_ih[orig(p),e] + bias[orig(p)]
// tf32 mma GEMM, 128x64 CTA tile, BK=16, double-buffered.
// Smem layout: row-major [m][k] with row stride 20 u32 (80B) -> the 8 row
// addresses of each ldmatrix cover all 32 banks once (conflict-free), and
// the STS side is one coalesced STS.128 per thread.
// ---------------------------------------------------------------------------
#define A_STRIDE 20
#define B_STRIDE 20
#define NITER 19   // ceil(300/16)

__global__ void gemm_P_kernel(const float* __restrict__ emb,
                              const float* __restrict__ W_ih,
                              const float* __restrict__ b_ih,
                              const float* __restrict__ b_hh) {
    __shared__ float As[2][128 * A_STRIDE];
    __shared__ float Bs[2][64 * B_STRIDE];

    const int m0 = blockIdx.y * 128;
    const int n0 = blockIdx.x * 64;   // permuted-column block
    const int tid = threadIdx.x;
    const int lane = tid & 31;
    const int wid = tid >> 5;
    const int warp_m = wid & 3;
    const int warp_n = wid >> 2;

    float acc[2][4][4];
#pragma unroll
    for (int mt = 0; mt < 2; mt++)
#pragma unroll
        for (int nt = 0; nt < 4; nt++)
#pragma unroll
            for (int c = 0; c < 4; c++) acc[mt][nt][c] = 0.f;

    float4 ra[2], rb;
    const int aq = tid & 3;        // k-quarter (4 floats each)
    const int am0 = (tid >> 2);    // A row (0..63), +64 for slab 1
    const int bn = tid >> 2;       // B row (0..63)
    const int gn_p = n0 + bn;
    const int gn_orig = (gn_p & 3) * 100 + (gn_p >> 2);

    // ldmatrix lane address components
    const int lr = lane & 7;
    const int lhalf = (lane >> 3) & 1;   // +8 rows (matrices 1,3)
    const int lkh = (lane >> 4) & 1;     // +4 cols  (matrices 2,3)
    const int l4 = lane & 15;
    const int br = l4 & 7;
    const int bkh = (l4 >> 3) & 1;

    auto loadAB = [&](int it) {
        int k0 = it * 16;
#pragma unroll
        for (int i = 0; i < 2; i++) {
            int m = am0 + i * 64;
            int gm = m0 + m;
            int gk = k0 + aq * 4;
            ra[i] = make_float4(0.f, 0.f, 0.f, 0.f);
            if (gm < VV && gk < EE)
                ra[i] = *reinterpret_cast<const float4*>(&emb[gm * EE + gk]);
        }
        int gk = k0 + aq * 4;
        rb = make_float4(0.f, 0.f, 0.f, 0.f);
        if (gn_p < GG && gk < EE)
            rb = *reinterpret_cast<const float4*>(&W_ih[gn_orig * EE + gk]);
    };

    loadAB(0);

    for (int it = 0; it < NITER; it++) {
        const int buf = it & 1;
        // coalesced STS.128 (raw f32 bits; HW reads tf32 from high bits)
        *reinterpret_cast<float4*>(&As[buf][am0 * A_STRIDE + aq * 4]) = ra[0];
        *reinterpret_cast<float4*>(&As[buf][(am0 + 64) * A_STRIDE + aq * 4]) = ra[1];
        *reinterpret_cast<float4*>(&Bs[buf][bn * B_STRIDE + aq * 4]) = rb;
        __syncthreads();

        if (it + 1 < NITER) loadAB(it + 1);

        const unsigned aBase = (unsigned)__cvta_generic_to_shared(
            &As[buf][(warp_m * 32 + lhalf * 8 + lr) * A_STRIDE + lkh * 4]);
        const unsigned bBase = (unsigned)__cvta_generic_to_shared(
            &Bs[buf][(warp_n * 32 + br) * B_STRIDE + bkh * 4]);

#pragma unroll
        for (int kt = 0; kt < 2; kt++) {
            unsigned afr[2][4];
            ldsm_x4(afr[0], aBase + kt * 32);
            ldsm_x4(afr[1], aBase + 16 * A_STRIDE * 4 + kt * 32);
            unsigned bfr[4][2];
#pragma unroll
            for (int nt = 0; nt < 4; nt++)
                ldsm_x2(bfr[nt], bBase + nt * 8 * B_STRIDE * 4 + kt * 32);
#pragma unroll
            for (int mt = 0; mt < 2; mt++)
#pragma unroll
                for (int nt = 0; nt < 4; nt++)
                    mma_tf32(acc[mt][nt], afr[mt], bfr[nt]);
        }
        __syncthreads();
    }

    // epilogue: bias (orig index) + contiguous float2 store at permuted cols
#pragma unroll
    for (int nt = 0; nt < 4; nt++) {
        int col = n0 + warp_n * 32 + nt * 8 + (lane & 3) * 2;   // permuted
        if (col >= GG) continue;
        int o0 = (col & 3) * 100 + (col >> 2);
        int o1 = ((col + 1) & 3) * 100 + ((col + 1) >> 2);
        float ba = b_ih[o0] + b_hh[o0];
        float bb = b_ih[o1] + b_hh[o1];
#pragma unroll
        for (int mt = 0; mt < 2; mt++) {
            int row0 = m0 + warp_m * 32 + mt * 16 + (lane >> 2);
            if (row0 < VV) {
                float2 v = make_float2(acc[mt][nt][0] + ba, acc[mt][nt][1] + bb);
                *reinterpret_cast<float2*>(&g_P[(size_t)row0 * GG + col]) = v;
            }
            int row1 = row0 + 8;
            if (row1 < VV) {
                float2 v = make_float2(acc[mt][nt][2] + ba, acc[mt][nt][3] + bb);
                *reinterpret_cast<float2*>(&g_P[(size_t)row1 * GG + col]) = v;
            }
        }
    }
}

// ---------------------------------------------------------------------------
// Kernel 2: label_vec[b] = emb[label_word_id[b]] @ ll_W^T + ll_b
// ---------------------------------------------------------------------------
__global__ void label_kernel(const int* __restrict__ label_word_id,
                             const float* __restrict__ emb,
                             const float* __restrict__ ll_W,
                             const float* __restrict__ ll_b) {
    __shared__ float row[EE];
    const int b = blockIdx.x;
    const int w = label_word_id[b];
    for (int e = threadIdx.x; e < EE; e += blockDim.x) row[e] = emb[w * EE + e];
    __syncthreads();
    const int j = threadIdx.x;
    if (j < HH) {
        float s = ll_b[j];
        const float* wr = &ll_W[j * EE];
        for (int e = 0; e < EE; e++) s += row[e] * wr[e];
        g_label[b * HH + j] = s;
    }
}

__global__ void probe_kernel() {
    if (threadIdx.x == 0) g_probe = 0.f;
}

// ---------------------------------------------------------------------------
// Kernel 3: LSTM recurrence. 128 CTAs x NB=8, 576 threads (18 warps).
//  - W_hh fragments for tiles 0,1 in REGISTERS; 3rd tile streams from smem
//  - only h streams through smem fragments; ONE __syncthreads per step.
// (unchanged from round 9 -- measured best)
// ---------------------------------------------------------------------------
__global__ void __launch_bounds__(LSTM_THREADS, 1)
lstm_kernel(const int* __restrict__ word_id,
            const int* __restrict__ sen_len,
            const float* __restrict__ W_hh) {
    __shared__ unsigned Hf[2][KTILES * 64];
    __shared__ unsigned Bs3[14 * KTILES * 64];   // 3rd-tile B frags for 14 warps
    __shared__ int rows[2][NB];
    __shared__ int senl[NB];

    const int tid = threadIdx.x;
    const int b0 = blockIdx.x * NB;
    const int lane = tid & 31;
    const int w = tid >> 5;
    const int nb = lane >> 2;
    const int cl2 = 2 * (lane & 3);

    const int ntc = (w == 12 || w == 13 || w == 16 || w == 17) ? 2 : 3;
    const int base = 3 * w - (w > 12) - (w > 13) - (w > 16) - (w > 17);
    const int slot3 = (w < 12) ? w : w - 2;
    const unsigned* Bs3w = &Bs3[slot3 * KTILES * 64];

    unsigned Breg[2][KTILES][2];
#pragma unroll
    for (int i = 0; i < 2; i++) {
        int nt = base + i;
        int n_perm = nt * 8 + (lane >> 2);
        int orig_n = (n_perm & 3) * 100 + (n_perm >> 2);
        const float* wr = &W_hh[orig_n * HH];
#pragma unroll
        for (int kt = 0; kt < KTILES; kt++) {
            int k0 = kt * 8 + (lane & 3);
            int k1 = k0 + 4;
            Breg[i][kt][0] = (k0 < HH) ? f2tf32(wr[k0]) : 0u;
            Breg[i][kt][1] = (k1 < HH) ? f2tf32(wr[k1]) : 0u;
        }
    }
    if (ntc == 3) {
        int nt = base + 2;
        int n_perm = nt * 8 + (lane >> 2);
        int orig_n = (n_perm & 3) * 100 + (n_perm >> 2);
        const float* wr = &W_hh[orig_n * HH];
        for (int kt = 0; kt < KTILES; kt++) {
            int k0 = kt * 8 + (lane & 3);
            int k1 = k0 + 4;
            unsigned v0 = (k0 < HH) ? f2tf32(wr[k0]) : 0u;
            unsigned v1 = (k1 < HH) ? f2tf32(wr[k1]) : 0u;
            Bs3[slot3 * KTILES * 64 + kt * 64 + lane * 2]     = v0;
            Bs3[slot3 * KTILES * 64 + kt * 64 + lane * 2 + 1] = v1;
        }
    }

    for (int idx = tid; idx < KTILES * 64; idx += LSTM_THREADS) Hf[0][idx] = 0u;
    if (tid < NB) {
        senl[tid] = sen_len[b0 + tid];
        rows[0][tid] = word_id[(b0 + tid) * TT];
    }
    __syncthreads();

    float cst[2] = {0.f, 0.f};

    for (int t = 0; t < TT; t++) {
        const int buf = t & 1;

        float2 pv[3];
        {
            const float* Prow = &g_P[(size_t)rows[buf][nb] * GG];
            pv[0] = *reinterpret_cast<const float2*>(&Prow[(base + 0) * 8 + cl2]);
            pv[1] = *reinterpret_cast<const float2*>(&Prow[(base + 1) * 8 + cl2]);
            if (ntc == 3)
                pv[2] = *reinterpret_cast<const float2*>(&Prow[(base + 2) * 8 + cl2]);
        }

        float acc[3][4];
#pragma unroll
        for (int i = 0; i < 3; i++) {
            acc[i][0] = 0.f; acc[i][1] = 0.f; acc[i][2] = 0.f; acc[i][3] = 0.f;
        }

#pragma unroll
        for (int kt = 0; kt < KTILES; kt++) {
            uint2 hv = *reinterpret_cast<const uint2*>(&Hf[buf][(kt * 32 + lane) * 2]);
            mma_tf32_half4(acc[0], hv.x, hv.y, Breg[0][kt][0], Breg[0][kt][1]);
            mma_tf32_half4(acc[1], hv.x, hv.y, Breg[1][kt][0], Breg[1][kt][1]);
            if (ntc == 3) {
                uint2 bv = *reinterpret_cast<const uint2*>(&Bs3w[kt * 64 + lane * 2]);
                mma_tf32_half4(acc[2], hv.x, hv.y, bv.x, bv.y);
            }
        }
        acc[0][0] += pv[0].x; acc[0][1] += pv[0].y;
        acc[1][0] += pv[1].x; acc[1][1] += pv[1].y;
        if (ntc == 3) { acc[2][0] += pv[2].x; acc[2][1] += pv[2].y; }

        const bool odd = (lane & 1);
        const int jsel = (lane >> 1) & 1;
#pragma unroll
        for (int bundle = 0; bundle < 2; bundle++) {
            if (bundle == 1 && ntc < 3) break;
            const int iA = (bundle == 0) ? 0 : 2;
            const int iB = (bundle == 0) ? 1 : 2;
            float xA0 = __shfl_xor_sync(0xffffffffu, acc[iA][0], 1);
            float xA1 = __shfl_xor_sync(0xffffffffu, acc[iA][1], 1);
            float xB0 = __shfl_xor_sync(0xffffffffu, acc[iB][0], 1);
            float xB1 = __shfl_xor_sync(0xffffffffu, acc[iB][1], 1);
            float gi = odd ? xB0 : acc[iA][0];
            float gf = odd ? xB1 : acc[iA][1];
            float gg = odd ? acc[iB][0] : xA0;
            float go = odd ? acc[iB][1] : xA1;
            int nt = base + (odd ? iB : iA);
            int j = 2 * nt + jsel;

            float si = sigm_hw(gi);
            float sf = sigm_hw(gf);
            float so = sigm_hw(go);
            float sg = tanh_hw(gg);
            float cv = sf * cst[bundle] + si * sg;
            cst[bundle] = cv;
            float h = so * tanh_hw(cv);

            if (!(iA == iB && odd)) {
                int jl = j & 7, kt = j >> 3;
                Hf[1 - buf][(kt * 32 + ((nb << 2) | (jl & 3))) * 2 + ((jl >> 2) & 1)]
                    = f2tf32(h);
                g_out[((size_t)(b0 + nb) * TT + t) * HH + j] = h;
                if (t == senl[nb] - 1) g_last[(b0 + nb) * HH + j] = h;
            }
        }

        if (tid < NB && t + 1 < TT)
            rows[1 - buf][tid] = word_id[(b0 + tid) * TT + t + 1];
        __syncthreads();
    }
}

// ---------------------------------------------------------------------------
// Kernel 4: per-batch epilogue: scores, top-4, pos, per_neg, out_f, l_rep, q.
// ---------------------------------------------------------------------------
__global__ void catch_kernel(const int* __restrict__ sen_len,
                             const float* __restrict__ lin_W,
                             const float* __restrict__ lin_b,
                             float* __restrict__ dout) {
    __shared__ float label_s[HH];
    __shared__ float last_s[HH];
    __shared__ float scores[TT];
    __shared__ float red_v[TT];
    __shared__ int   red_i[TT];
    __shared__ float topv[4];
    __shared__ int   topi[4];
    __shared__ float pos_s[HH];
    __shared__ float pneg_s[HH];

    const int b = blockIdx.x;
    const int tid = threadIdx.x;
    const int L = sen_len[b];

    if (tid < HH) {
        label_s[tid] = g_label[b * HH + tid];
        last_s[tid]  = g_last[b * HH + tid];
    }
    __syncthreads();

    {
        float s;
        if (tid < L) {
            s = 0.f;
            const float* o = &g_out[((size_t)b * TT + tid) * HH];
            for (int j = 0; j < HH; j++) s += o[j] * label_s[j];
        } else {
            s = -1e30f;
        }
        scores[tid] = s;
    }
    __syncthreads();

    for (int k = 0; k < 4; k++) {
        red_v[tid] = scores[tid];
        red_i[tid] = tid;
        __syncthreads();
        for (int off = TT / 2; off > 0; off >>= 1) {
            if (tid < off) {
                float v2 = red_v[tid + off];
                int   i2 = red_i[tid + off];
                if (v2 > red_v[tid] || (v2 == red_v[tid] && i2 < red_i[tid])) {
                    red_v[tid] = v2;
                    red_i[tid] = i2;
                }
            }
            __syncthreads();
        }
        if (tid == 0) {
            topv[k] = red_v[0];
            topi[k] = red_i[0];
            scores[red_i[0]] = -1e30f;
        }
        __syncthreads();
    }

    if (tid < HH) {
        float p = 0.f;
#pragma unroll
        for (int k = 0; k < 4; k++)
            p += g_out[((size_t)b * TT + topi[k]) * HH + tid] * topv[k];
        pos_s[tid] = p;

        float s = 0.f;
        int i0 = topi[0], i1 = topi[1], i2 = topi[2], i3 = topi[3];
        for (int t = 0; t < L; t++) {
            if (t == i0 || t == i1 || t == i2 || t == i3) continue;
            s += g_out[((size_t)b * TT + t) * HH + tid];
        }
        pneg_s[tid] = s;
    }
    __syncthreads();

    if (tid < 6) {
        float bo = lin_b[tid];
        float o = bo, l = bo, q = 0.f;
        const float* wv = &lin_W[tid * HH];
        for (int j = 0; j < HH; j++) {
            float wj = wv[j];
            o += last_s[j] * wj;
            l += pos_s[j] * wj;
            q += pneg_s[j] * wj;
        }
        dout[b * 6 + tid] = o;
        dout[BB * 6 + b * 6 + tid] = l;
        g_q[b * 6 + tid] = q;
    }
}

// ---------------------------------------------------------------------------
// Kernel 5: r_rep = cumsum over batch of q + lin_b (warp-parallel scan).
// ---------------------------------------------------------------------------
__global__ void scan_kernel(const float* __restrict__ lin_b,
                            float* __restrict__ dout) {
    const int w = threadIdx.x >> 5;
    const int l = threadIdx.x & 31;
    if (w >= 6) return;
    float run = lin_b[w];
    for (int c0 = 0; c0 < BB; c0 += 32) {
        float v = g_q[(c0 + l) * 6 + w];
#pragma unroll
        for (int off = 1; off < 32; off <<= 1) {
            float u = __shfl_up_sync(0xffffffff, v, off);
            if (l >= off) v += u;
        }
        dout[2 * BB * 6 + (c0 + l) * 6 + w] = run + v;
        run += __shfl_sync(0xffffffff, v, 31);
    }
}

// ---------------------------------------------------------------------------
extern "C" void kernel_launch(void* const* d_in, const int* in_sizes, int n_in,
                              void* d_out, int out_size) {
    const int*   word_id       = (const int*)d_in[0];
    const int*   sen_len       = (const int*)d_in[1];
    const int*   label_word_id = (const int*)d_in[2];
    const float* emb           = (const float*)d_in[3];
    const float* W_ih          = (const float*)d_in[4];
    const float* W_hh          = (const float*)d_in[5];
    const float* b_ih          = (const float*)d_in[6];
    const float* b_hh          = (const float*)d_in[7];
    const float* lin_W         = (const float*)d_in[8];
    const float* lin_b         = (const float*)d_in[9];
    const float* ll_W          = (const float*)d_in[10];
    const float* ll_b          = (const float*)d_in[11];
    float* out = (float*)d_out;

    dim3 ggrid((GG + 63) / 64, (VV + 127) / 128);   // n fastest -> A slab L2 reuse
    // ncu captures launch index 3 -> keep gemm_P there to verify the ldmatrix fix.
    probe_kernel<<<1, 32>>>();                                       // idx 0
    probe_kernel<<<1, 32>>>();                                       // idx 1
    probe_kernel<<<1, 32>>>();                                       // idx 2
    gemm_P_kernel<<<ggrid, 256>>>(emb, W_ih, b_ih, b_hh);            // idx 3 (profiled)
    label_kernel<<<BB, 128>>>(label_word_id, emb, ll_W, ll_b);       // idx 4
    lstm_kernel<<<BB / NB, LSTM_THREADS>>>(word_id, sen_len, W_hh);  // idx 5
    catch_kernel<<<BB, 128>>>(sen_len, lin_W, lin_b, out);           // idx 6
    scan_kernel<<<1, 192>>>(lin_b, out);                             // idx 7
}